// round 15
// baseline (speedup 1.0000x reference)
#include <cuda_runtime.h>
#include <cuda_fp16.h>
#include <cstdint>

#define K_DIM 1024
#define N_DIM 1024
#define MAX_M 65536

// ---------------------------------------------------------------------------
// Scratch (device globals — no allocation APIs allowed)
// ---------------------------------------------------------------------------
__device__ __half g_A[(size_t)MAX_M * K_DIM];
__device__ __half g_B[(size_t)N_DIM * K_DIM];

__device__ __forceinline__ uint32_t smem_u32(const void* p) {
    uint32_t a;
    asm("{ .reg .u64 t; cvta.to.shared.u64 t, %1; cvt.u32.u64 %0, t; }"
        : "=r"(a) : "l"(p));
    return a;
}

__device__ __forceinline__ void cp_async16(uint32_t saddr, const void* gaddr) {
    asm volatile("cp.async.cg.shared.global [%0], [%1], 16;"
                 :: "r"(saddr), "l"(gaddr) : "memory");
}

__device__ __forceinline__ void ldsm_x4(uint32_t addr, uint32_t& r0, uint32_t& r1,
                                        uint32_t& r2, uint32_t& r3) {
    asm volatile("ldmatrix.sync.aligned.m8n8.x4.shared.b16 {%0,%1,%2,%3}, [%4];"
                 : "=r"(r0), "=r"(r1), "=r"(r2), "=r"(r3) : "r"(addr));
}

// fp16-accumulate mma: D/C are 2 packed half2 regs. 2x the f32-acc rate.
__device__ __forceinline__ void mma16816_f16(uint32_t& c0, uint32_t& c1,
                                             const uint32_t* a,
                                             uint32_t b0, uint32_t b1) {
    asm volatile(
        "mma.sync.aligned.m16n8k16.row.col.f16.f16.f16.f16 "
        "{%0,%1}, {%2,%3,%4,%5}, {%6,%7}, {%0,%1};"
        : "+r"(c0), "+r"(c1)
        : "r"(a[0]), "r"(a[1]), "r"(a[2]), "r"(a[3]), "r"(b0), "r"(b1));
}

#define CLUSTER_SYNC_ASM() do {                                         \
    asm volatile("barrier.cluster.arrive.aligned;" ::: "memory");       \
    asm volatile("barrier.cluster.wait.aligned;" ::: "memory");         \
} while (0)

// ---------------------------------------------------------------------------
// Kernel 1: fp16 convert of m (1024x1024).
// ---------------------------------------------------------------------------
__global__ void convertB_kernel(const float* __restrict__ m) {
    const size_t i = (size_t)blockIdx.x * 256 + threadIdx.x;  // 262144 float4s
    float4 v = reinterpret_cast<const float4*>(m)[i];
    __half2* ph = reinterpret_cast<__half2*>(g_B);
    ph[2 * i]     = __halves2half2(__float2half_rn(v.x), __float2half_rn(v.y));
    ph[2 * i + 1] = __halves2half2(__float2half_rn(v.z), __float2half_rn(v.w));
}

// ---------------------------------------------------------------------------
// Kernel 2: fully-fused GEMM (round-11 base: fused convertA prologue,
// 128x128 CTA tile, BK=64, 8 warps 4m x 2n, 3-stage cp.async, 96 KB SMEM,
// 2 CTAs/SM, cluster epilogue). This round: fp16-ACCUMULATE mma within each
// K=64 chunk (rt=4, halves the tensor floor) + per-chunk fp32 promotion.
// Error budget: +~3e-4 rel (16 chunks x 4 rounded fp16 writebacks).
// ---------------------------------------------------------------------------
#define TILE_B 16384
#define STAGE_B (2 * TILE_B)
#define NSTAGE 3
#define SMEM_TOTAL (NSTAGE * STAGE_B)   // 96 KB
#define CLUSTER_X 8

__global__ __launch_bounds__(256, 2) void gemm_hmma(float* __restrict__ C,
                                                    const float* __restrict__ X) {
    extern __shared__ char smem[];
    const uint32_t sb = smem_u32(smem);
    const int tid = threadIdx.x;
    const int wid = tid >> 5, lid = tid & 31;
    const int wm = wid & 3, wn = wid >> 2;        // warp grid 4(m) x 2(n)
    const int bm = blockIdx.y << 7, bn = blockIdx.x << 7;

    uint32_t myrank;
    asm("mov.u32 %0, %%cluster_ctarank;" : "=r"(myrank));

    // ===================== fused convertA prologue =====================
    {
#pragma unroll
        for (int rr = 0; rr < 2; rr++) {
            const int row = bm + (int)(myrank << 4) + (wid << 1) + rr;
            const float4* xr =
                reinterpret_cast<const float4*>(X + ((size_t)row << 10));
            float4 v[8];
            float ss = 0.0f;
#pragma unroll
            for (int j = 0; j < 8; j++) {
                float4 t = xr[lid + (j << 5)];
                t.x = (t.x == t.x) ? t.x : 0.0f;
                t.y = (t.y == t.y) ? t.y : 0.0f;
                t.z = (t.z == t.z) ? t.z : 0.0f;
                t.w = (t.w == t.w) ? t.w : 0.0f;
                v[j] = t;
                ss += t.x * t.x + t.y * t.y + t.z * t.z + t.w * t.w;
            }
#pragma unroll
            for (int o = 16; o > 0; o >>= 1)
                ss += __shfl_xor_sync(0xFFFFFFFFu, ss, o);

            float pn = fmaxf(sqrtf(ss), 1e-15f);
            float arg = fminf(pn, 0.99f - 1e-7f);
            arg = fmaxf(arg, -0.99f + 1e-7f);
            float at = 0.5f * (log1pf(arg) - log1pf(-arg));
            const float s = at / pn;

            uint2* ph = reinterpret_cast<uint2*>(g_A + ((size_t)row << 10));
#pragma unroll
            for (int j = 0; j < 8; j++) {
                float4 t = v[j];
                __half2 h0 = __halves2half2(
                    __float2half_rn(fminf(fmaxf(t.x * s, -50.0f), 50.0f)),
                    __float2half_rn(fminf(fmaxf(t.y * s, -50.0f), 50.0f)));
                __half2 h1 = __halves2half2(
                    __float2half_rn(fminf(fmaxf(t.z * s, -50.0f), 50.0f)),
                    __float2half_rn(fminf(fmaxf(t.w * s, -50.0f), 50.0f)));
                uint2 u;
                u.x = *reinterpret_cast<uint32_t*>(&h0);
                u.y = *reinterpret_cast<uint32_t*>(&h1);
                ph[lid + (j << 5)] = u;
            }
        }
    }
    __threadfence();
    CLUSTER_SYNC_ASM();

    // ========================== GEMM mainloop ==========================
    auto load_stage = [&](int st, int k0) {
        const uint32_t sbase = sb + st * STAGE_B;
#pragma unroll
        for (int t = 0; t < 2; t++) {
            const __half* g = t ? g_B : g_A;
            const int rb = t ? bn : bm;
            const uint32_t sdst = sbase + t * TILE_B;
#pragma unroll
            for (int i = 0; i < 4; i++) {
                int idx = tid + (i << 8);
                int r = idx >> 3;
                int c16 = idx & 7;
                uint32_t boff = (uint32_t)((r << 7) + (c16 << 4));
                uint32_t sw = boff ^ ((boff >> 3) & 0x70);
                cp_async16(sdst + sw,
                           g + ((size_t)(rb + r) << 10) + k0 + (c16 << 3));
            }
        }
        asm volatile("cp.async.commit_group;" ::: "memory");
    };

    const int lr = lid & 15;
    const uint32_t khalf = (uint32_t)((lid >> 4) << 4);
    uint32_t rA[2], xA[2], rB[4], xB[4];
#pragma unroll
    for (int i = 0; i < 2; i++) {
        int r = wm * 32 + i * 16 + lr;
        rA[i] = (uint32_t)(r << 7);
        xA[i] = (uint32_t)((r & 7) << 4);
    }
#pragma unroll
    for (int j = 0; j < 4; j++) {
        int r = wn * 64 + j * 16 + lr;
        rB[j] = (uint32_t)(r << 7);
        xB[j] = (uint32_t)((r & 7) << 4);
    }

    float acc[2][8][4];
#pragma unroll
    for (int i = 0; i < 2; i++)
#pragma unroll
        for (int j = 0; j < 8; j++)
#pragma unroll
            for (int q = 0; q < 4; q++) acc[i][j][q] = 0.0f;

    load_stage(0, 0);
    load_stage(1, 64);

    int st = 0;

    auto do_chunk = [&]() {
        const uint32_t stb = sb + st * STAGE_B;
        const uint32_t tA = stb, tB = stb + TILE_B;

        // fp16 chunk accumulators (zeroed each chunk)
        uint32_t acch[2][8][2];
#pragma unroll
        for (int i = 0; i < 2; i++)
#pragma unroll
            for (int j = 0; j < 8; j++) {
                acch[i][j][0] = 0u;
                acch[i][j][1] = 0u;
            }

#pragma unroll
        for (int kk = 0; kk < 4; kk++) {
            const uint32_t kb = (uint32_t)(kk << 5) + khalf;
            uint32_t a[2][4];
#pragma unroll
            for (int i = 0; i < 2; i++)
                ldsm_x4(tA + rA[i] + (kb ^ xA[i]),
                        a[i][0], a[i][1], a[i][2], a[i][3]);
#pragma unroll
            for (int j4 = 0; j4 < 4; j4++) {
                uint32_t r0, r1, r2, r3;
                ldsm_x4(tB + rB[j4] + (kb ^ xB[j4]), r0, r1, r2, r3);
                // pair j=2*j4 uses {r0,r2}; j=2*j4+1 uses {r1,r3}
#pragma unroll
                for (int i = 0; i < 2; i++) {
                    mma16816_f16(acch[i][2 * j4][0], acch[i][2 * j4][1],
                                 a[i], r0, r2);
                    mma16816_f16(acch[i][2 * j4 + 1][0], acch[i][2 * j4 + 1][1],
                                 a[i], r1, r3);
                }
            }
        }

        // promote chunk partials to fp32 accumulators
#pragma unroll
        for (int i = 0; i < 2; i++)
#pragma unroll
            for (int j = 0; j < 8; j++) {
                float2 f0 = __half22float2(
                    *reinterpret_cast<__half2*>(&acch[i][j][0]));
                float2 f1 = __half22float2(
                    *reinterpret_cast<__half2*>(&acch[i][j][1]));
                acc[i][j][0] += f0.x;
                acc[i][j][1] += f0.y;
                acc[i][j][2] += f1.x;
                acc[i][j][3] += f1.y;
            }

        st = st + 1; if (st >= NSTAGE) st = 0;
    };

    for (int c = 0; c < 15; ++c) {
        asm volatile("cp.async.wait_group 1;" ::: "memory");
        __syncthreads();
        if (c + 2 < 16) {
            int st2 = st + 2; if (st2 >= NSTAGE) st2 -= NSTAGE;
            load_stage(st2, (c + 2) << 6);
        }
        do_chunk();
    }
    asm volatile("cp.async.wait_group 0;" ::: "memory");
    __syncthreads();
    do_chunk();

    // ======================= fused cluster epilogue =======================
    float* sp = reinterpret_cast<float*>(smem);

#pragma unroll
    for (int i = 0; i < 2; i++)
#pragma unroll
        for (int j = 0; j < 8; j++)
#pragma unroll
            for (int q = 0; q < 4; q++)
                acc[i][j][q] = fminf(fmaxf(acc[i][j][q], -1000.0f), 1000.0f);

    __syncthreads();

#pragma unroll
    for (int i = 0; i < 2; i++) {
        float s01 = 0.0f, s23 = 0.0f;
#pragma unroll
        for (int j = 0; j < 8; j++) {
            s01 += acc[i][j][0] * acc[i][j][0] + acc[i][j][1] * acc[i][j][1];
            s23 += acc[i][j][2] * acc[i][j][2] + acc[i][j][3] * acc[i][j][3];
        }
        s01 += __shfl_xor_sync(0xFFFFFFFFu, s01, 1);
        s01 += __shfl_xor_sync(0xFFFFFFFFu, s01, 2);
        s23 += __shfl_xor_sync(0xFFFFFFFFu, s23, 1);
        s23 += __shfl_xor_sync(0xFFFFFFFFu, s23, 2);
        if ((lid & 3) == 0) {
            int lrow = wm * 32 + i * 16 + (lid >> 2);
            sp[wn * 128 + lrow] = s01;
            sp[wn * 128 + lrow + 8] = s23;
        }
    }
    __syncthreads();

    CLUSTER_SYNC_ASM();

    if (tid < 128) {
        float val = sp[tid] + sp[128 + tid];
        uint32_t laddr = sb + (256 + myrank * 128 + tid) * 4;
#pragma unroll
        for (int rk = 0; rk < CLUSTER_X; rk++) {
            uint32_t raddr;
            asm("mapa.shared::cluster.u32 %0, %1, %2;"
                : "=r"(raddr) : "r"(laddr), "r"(rk));
            asm volatile("st.shared::cluster.f32 [%0], %1;"
                         :: "r"(raddr), "f"(val) : "memory");
        }
    }

    CLUSTER_SYNC_ASM();

    if (tid < 128) {
        float ss = 0.0f;
#pragma unroll
        for (int rk = 0; rk < CLUSTER_X; rk++) ss += sp[256 + rk * 128 + tid];
        const float un = fmaxf(sqrtf(ss), 1e-15f);
        const float th = tanhf(un);
        float f = th / un;
        const float max_norm = (float)(1.0 - 1e-10);
        if (th > max_norm) f *= max_norm / fmaxf(th, 1e-9f);
        sp[1280 + tid] = f;
    }
    __syncthreads();

    const int r0 = bm + wm * 32 + (lid >> 2);
    const int lrow0 = wm * 32 + (lid >> 2);
    const int c0 = bn + wn * 64 + ((lid & 3) << 1);
#pragma unroll
    for (int i = 0; i < 2; i++) {
        const float f01 = sp[1280 + lrow0 + i * 16];
        const float f23 = sp[1280 + lrow0 + i * 16 + 8];
#pragma unroll
        for (int j = 0; j < 8; j++) {
            size_t base = ((size_t)(r0 + i * 16) << 10) + c0 + j * 8;
            *reinterpret_cast<float2*>(C + base) =
                make_float2(acc[i][j][0] * f01, acc[i][j][1] * f01);
            *reinterpret_cast<float2*>(C + base + (8 << 10)) =
                make_float2(acc[i][j][2] * f23, acc[i][j][3] * f23);
        }
    }
}

// ---------------------------------------------------------------------------
extern "C" void kernel_launch(void* const* d_in, const int* in_sizes, int n_in,
                              void* d_out, int out_size) {
    const float* x = (const float*)d_in[0];   // [M, 1024]
    const float* m = (const float*)d_in[1];   // [1024, 1024]
    float* out = (float*)d_out;               // [M, 1024] f32

    int M = in_sizes[0] / K_DIM;
    if (M > MAX_M) M = MAX_M;

    cudaFuncSetAttribute(gemm_hmma, cudaFuncAttributeMaxDynamicSharedMemorySize,
                         SMEM_TOTAL);

    convertB_kernel<<<1024, 256>>>(m);

    cudaLaunchConfig_t cfg = {};
    cfg.gridDim = dim3(N_DIM / 128, M / 128, 1);
    cfg.blockDim = dim3(256, 1, 1);
    cfg.dynamicSmemBytes = SMEM_TOTAL;
    cfg.stream = 0;
    cudaLaunchAttribute attrs[1];
    attrs[0].id = cudaLaunchAttributeClusterDimension;
    attrs[0].val.clusterDim.x = CLUSTER_X;
    attrs[0].val.clusterDim.y = 1;
    attrs[0].val.clusterDim.z = 1;
    cfg.attrs = attrs;
    cfg.numAttrs = 1;
    cudaLaunchKernelEx(&cfg, gemm_hmma, out, x);
}

// round 16
// speedup vs baseline: 1.2531x; 1.2531x over previous
#include <cuda_runtime.h>
#include <cuda_fp16.h>
#include <cstdint>

#define K_DIM 1024
#define N_DIM 1024
#define MAX_M 65536

// ---------------------------------------------------------------------------
// Scratch (device globals — no allocation APIs allowed)
// ---------------------------------------------------------------------------
__device__ __half g_A[(size_t)MAX_M * K_DIM];
__device__ __half g_B[(size_t)N_DIM * K_DIM];

__device__ __forceinline__ uint32_t smem_u32(const void* p) {
    uint32_t a;
    asm("{ .reg .u64 t; cvta.to.shared.u64 t, %1; cvt.u32.u64 %0, t; }"
        : "=r"(a) : "l"(p));
    return a;
}

__device__ __forceinline__ void cp_async16(uint32_t saddr, const void* gaddr) {
    asm volatile("cp.async.cg.shared.global [%0], [%1], 16;"
                 :: "r"(saddr), "l"(gaddr) : "memory");
}

__device__ __forceinline__ void ldsm_x4(uint32_t addr, uint32_t& r0, uint32_t& r1,
                                        uint32_t& r2, uint32_t& r3) {
    asm volatile("ldmatrix.sync.aligned.m8n8.x4.shared.b16 {%0,%1,%2,%3}, [%4];"
                 : "=r"(r0), "=r"(r1), "=r"(r2), "=r"(r3) : "r"(addr));
}

__device__ __forceinline__ void mma16816(float* c, const uint32_t* a,
                                         const uint32_t* b) {
    asm volatile(
        "mma.sync.aligned.m16n8k16.row.col.f32.f16.f16.f32 "
        "{%0,%1,%2,%3}, {%4,%5,%6,%7}, {%8,%9}, {%0,%1,%2,%3};"
        : "+f"(c[0]), "+f"(c[1]), "+f"(c[2]), "+f"(c[3])
        : "r"(a[0]), "r"(a[1]), "r"(a[2]), "r"(a[3]), "r"(b[0]), "r"(b[1]));
}

#define CLUSTER_SYNC_ASM() do {                                         \
    asm volatile("barrier.cluster.arrive.aligned;" ::: "memory");       \
    asm volatile("barrier.cluster.wait.aligned;" ::: "memory");         \
} while (0)

// ---------------------------------------------------------------------------
// Kernel 1: fp16 convert of m (1024x1024).
// ---------------------------------------------------------------------------
__global__ void convertB_kernel(const float* __restrict__ m) {
    const size_t i = (size_t)blockIdx.x * 256 + threadIdx.x;  // 262144 float4s
    float4 v = reinterpret_cast<const float4*>(m)[i];
    __half2* ph = reinterpret_cast<__half2*>(g_B);
    ph[2 * i]     = __halves2half2(__float2half_rn(v.x), __float2half_rn(v.y));
    ph[2 * i + 1] = __halves2half2(__float2half_rn(v.z), __float2half_rn(v.w));
}

// ---------------------------------------------------------------------------
// Kernel 2: fully-fused GEMM (final, round-11 proven configuration).
//  PROLOGUE (overlapped with co-resident CTA's mainloop): CTA rank r of each
//    8-CTA cluster converts x rows [bm+16r, bm+16r+16) -> logmap0-scaled
//    fp16 g_A; threadfence + cluster.sync.
//  MAINLOOP: 128x128 CTA tile, BK=64, 8 warps (4m x 2n, 32x64 warp tiles),
//    fp32-accumulate HMMA, 3-stage cp.async, 96 KB SMEM, 2 CTAs/SM.
//  EPILOGUE: cluster-wide row-sumsq exchange via DSMEM, tanh scale (+proj),
//    direct final store — no intermediate-C round trip.
// ---------------------------------------------------------------------------
#define TILE_B 16384
#define STAGE_B (2 * TILE_B)
#define NSTAGE 3
#define SMEM_TOTAL (NSTAGE * STAGE_B)   // 96 KB
#define CLUSTER_X 8

__global__ __launch_bounds__(256, 2) void gemm_hmma(float* __restrict__ C,
                                                    const float* __restrict__ X) {
    extern __shared__ char smem[];
    const uint32_t sb = smem_u32(smem);
    const int tid = threadIdx.x;
    const int wid = tid >> 5, lid = tid & 31;
    const int wm = wid & 3, wn = wid >> 2;        // warp grid 4(m) x 2(n)
    const int bm = blockIdx.y << 7, bn = blockIdx.x << 7;

    uint32_t myrank;
    asm("mov.u32 %0, %%cluster_ctarank;" : "=r"(myrank));

    // ===================== fused convertA prologue =====================
    {
#pragma unroll
        for (int rr = 0; rr < 2; rr++) {
            const int row = bm + (int)(myrank << 4) + (wid << 1) + rr;
            const float4* xr =
                reinterpret_cast<const float4*>(X + ((size_t)row << 10));
            float4 v[8];
            float ss = 0.0f;
#pragma unroll
            for (int j = 0; j < 8; j++) {
                float4 t = xr[lid + (j << 5)];
                t.x = (t.x == t.x) ? t.x : 0.0f;
                t.y = (t.y == t.y) ? t.y : 0.0f;
                t.z = (t.z == t.z) ? t.z : 0.0f;
                t.w = (t.w == t.w) ? t.w : 0.0f;
                v[j] = t;
                ss += t.x * t.x + t.y * t.y + t.z * t.z + t.w * t.w;
            }
#pragma unroll
            for (int o = 16; o > 0; o >>= 1)
                ss += __shfl_xor_sync(0xFFFFFFFFu, ss, o);

            float pn = fmaxf(sqrtf(ss), 1e-15f);
            float arg = fminf(pn, 0.99f - 1e-7f);
            arg = fmaxf(arg, -0.99f + 1e-7f);
            float at = 0.5f * (log1pf(arg) - log1pf(-arg));
            const float s = at / pn;

            uint2* ph = reinterpret_cast<uint2*>(g_A + ((size_t)row << 10));
#pragma unroll
            for (int j = 0; j < 8; j++) {
                float4 t = v[j];
                __half2 h0 = __halves2half2(
                    __float2half_rn(fminf(fmaxf(t.x * s, -50.0f), 50.0f)),
                    __float2half_rn(fminf(fmaxf(t.y * s, -50.0f), 50.0f)));
                __half2 h1 = __halves2half2(
                    __float2half_rn(fminf(fmaxf(t.z * s, -50.0f), 50.0f)),
                    __float2half_rn(fminf(fmaxf(t.w * s, -50.0f), 50.0f)));
                uint2 u;
                u.x = *reinterpret_cast<uint32_t*>(&h0);
                u.y = *reinterpret_cast<uint32_t*>(&h1);
                ph[lid + (j << 5)] = u;
            }
        }
    }
    __threadfence();
    CLUSTER_SYNC_ASM();

    // ========================== GEMM mainloop ==========================
    auto load_stage = [&](int st, int k0) {
        const uint32_t sbase = sb + st * STAGE_B;
#pragma unroll
        for (int t = 0; t < 2; t++) {
            const __half* g = t ? g_B : g_A;
            const int rb = t ? bn : bm;
            const uint32_t sdst = sbase + t * TILE_B;
#pragma unroll
            for (int i = 0; i < 4; i++) {
                int idx = tid + (i << 8);
                int r = idx >> 3;
                int c16 = idx & 7;
                uint32_t boff = (uint32_t)((r << 7) + (c16 << 4));
                uint32_t sw = boff ^ ((boff >> 3) & 0x70);
                cp_async16(sdst + sw,
                           g + ((size_t)(rb + r) << 10) + k0 + (c16 << 3));
            }
        }
        asm volatile("cp.async.commit_group;" ::: "memory");
    };

    const int lr = lid & 15;
    const uint32_t khalf = (uint32_t)((lid >> 4) << 4);
    uint32_t rA[2], xA[2], rB[4], xB[4];
#pragma unroll
    for (int i = 0; i < 2; i++) {
        int r = wm * 32 + i * 16 + lr;
        rA[i] = (uint32_t)(r << 7);
        xA[i] = (uint32_t)((r & 7) << 4);
    }
#pragma unroll
    for (int j = 0; j < 4; j++) {
        int r = wn * 64 + j * 16 + lr;
        rB[j] = (uint32_t)(r << 7);
        xB[j] = (uint32_t)((r & 7) << 4);
    }

    float acc[2][8][4];
#pragma unroll
    for (int i = 0; i < 2; i++)
#pragma unroll
        for (int j = 0; j < 8; j++)
#pragma unroll
            for (int q = 0; q < 4; q++) acc[i][j][q] = 0.0f;

    load_stage(0, 0);
    load_stage(1, 64);

    int st = 0;

    auto do_chunk = [&]() {
        const uint32_t stb = sb + st * STAGE_B;
        const uint32_t tA = stb, tB = stb + TILE_B;
#pragma unroll
        for (int kk = 0; kk < 4; kk++) {
            const uint32_t kb = (uint32_t)(kk * 32) + khalf;
            uint32_t a[2][4];
#pragma unroll
            for (int i = 0; i < 2; i++)
                ldsm_x4(tA + rA[i] + (kb ^ xA[i]),
                        a[i][0], a[i][1], a[i][2], a[i][3]);
            uint32_t b[8][2];
#pragma unroll
            for (int j = 0; j < 4; j++) {
                uint32_t r0, r1, r2, r3;
                ldsm_x4(tB + rB[j] + (kb ^ xB[j]), r0, r1, r2, r3);
                b[2 * j][0] = r0; b[2 * j + 1][0] = r1;
                b[2 * j][1] = r2; b[2 * j + 1][1] = r3;
            }
#pragma unroll
            for (int i = 0; i < 2; i++)
#pragma unroll
                for (int j = 0; j < 8; j++) mma16816(acc[i][j], a[i], b[j]);
        }
        st = st + 1; if (st >= NSTAGE) st = 0;
    };

    for (int c = 0; c < 15; ++c) {
        asm volatile("cp.async.wait_group 1;" ::: "memory");
        __syncthreads();
        if (c + 2 < 16) {
            int st2 = st + 2; if (st2 >= NSTAGE) st2 -= NSTAGE;
            load_stage(st2, (c + 2) << 6);
        }
        do_chunk();
    }
    asm volatile("cp.async.wait_group 0;" ::: "memory");
    __syncthreads();
    do_chunk();

    // ======================= fused cluster epilogue =======================
    float* sp = reinterpret_cast<float*>(smem);

#pragma unroll
    for (int i = 0; i < 2; i++)
#pragma unroll
        for (int j = 0; j < 8; j++)
#pragma unroll
            for (int q = 0; q < 4; q++)
                acc[i][j][q] = fminf(fmaxf(acc[i][j][q], -1000.0f), 1000.0f);

    __syncthreads();

#pragma unroll
    for (int i = 0; i < 2; i++) {
        float s01 = 0.0f, s23 = 0.0f;
#pragma unroll
        for (int j = 0; j < 8; j++) {
            s01 += acc[i][j][0] * acc[i][j][0] + acc[i][j][1] * acc[i][j][1];
            s23 += acc[i][j][2] * acc[i][j][2] + acc[i][j][3] * acc[i][j][3];
        }
        s01 += __shfl_xor_sync(0xFFFFFFFFu, s01, 1);
        s01 += __shfl_xor_sync(0xFFFFFFFFu, s01, 2);
        s23 += __shfl_xor_sync(0xFFFFFFFFu, s23, 1);
        s23 += __shfl_xor_sync(0xFFFFFFFFu, s23, 2);
        if ((lid & 3) == 0) {
            int lrow = wm * 32 + i * 16 + (lid >> 2);
            sp[wn * 128 + lrow] = s01;
            sp[wn * 128 + lrow + 8] = s23;
        }
    }
    __syncthreads();

    CLUSTER_SYNC_ASM();

    if (tid < 128) {
        float val = sp[tid] + sp[128 + tid];
        uint32_t laddr = sb + (256 + myrank * 128 + tid) * 4;
#pragma unroll
        for (int rk = 0; rk < CLUSTER_X; rk++) {
            uint32_t raddr;
            asm("mapa.shared::cluster.u32 %0, %1, %2;"
                : "=r"(raddr) : "r"(laddr), "r"(rk));
            asm volatile("st.shared::cluster.f32 [%0], %1;"
                         :: "r"(raddr), "f"(val) : "memory");
        }
    }

    CLUSTER_SYNC_ASM();

    if (tid < 128) {
        float ss = 0.0f;
#pragma unroll
        for (int rk = 0; rk < CLUSTER_X; rk++) ss += sp[256 + rk * 128 + tid];
        const float un = fmaxf(sqrtf(ss), 1e-15f);
        const float th = tanhf(un);
        float f = th / un;
        const float max_norm = (float)(1.0 - 1e-10);
        if (th > max_norm) f *= max_norm / fmaxf(th, 1e-9f);
        sp[1280 + tid] = f;
    }
    __syncthreads();

    const int r0 = bm + wm * 32 + (lid >> 2);
    const int lrow0 = wm * 32 + (lid >> 2);
    const int c0 = bn + wn * 64 + ((lid & 3) << 1);
#pragma unroll
    for (int i = 0; i < 2; i++) {
        const float f01 = sp[1280 + lrow0 + i * 16];
        const float f23 = sp[1280 + lrow0 + i * 16 + 8];
#pragma unroll
        for (int j = 0; j < 8; j++) {
            size_t base = ((size_t)(r0 + i * 16) << 10) + c0 + j * 8;
            *reinterpret_cast<float2*>(C + base) =
                make_float2(acc[i][j][0] * f01, acc[i][j][1] * f01);
            *reinterpret_cast<float2*>(C + base + (8 << 10)) =
                make_float2(acc[i][j][2] * f23, acc[i][j][3] * f23);
        }
    }
}

// ---------------------------------------------------------------------------
extern "C" void kernel_launch(void* const* d_in, const int* in_sizes, int n_in,
                              void* d_out, int out_size) {
    const float* x = (const float*)d_in[0];   // [M, 1024]
    const float* m = (const float*)d_in[1];   // [1024, 1024]
    float* out = (float*)d_out;               // [M, 1024] f32

    int M = in_sizes[0] / K_DIM;
    if (M > MAX_M) M = MAX_M;

    cudaFuncSetAttribute(gemm_hmma, cudaFuncAttributeMaxDynamicSharedMemorySize,
                         SMEM_TOTAL);

    convertB_kernel<<<1024, 256>>>(m);

    cudaLaunchConfig_t cfg = {};
    cfg.gridDim = dim3(N_DIM / 128, M / 128, 1);
    cfg.blockDim = dim3(256, 1, 1);
    cfg.dynamicSmemBytes = SMEM_TOTAL;
    cfg.stream = 0;
    cudaLaunchAttribute attrs[1];
    attrs[0].id = cudaLaunchAttributeClusterDimension;
    attrs[0].val.clusterDim.x = CLUSTER_X;
    attrs[0].val.clusterDim.y = 1;
    attrs[0].val.clusterDim.z = 1;
    cfg.attrs = attrs;
    cfg.numAttrs = 1;
    cudaLaunchKernelEx(&cfg, gemm_hmma, out, x);
}